// round 3
// baseline (speedup 1.0000x reference)
#include <cuda_runtime.h>
#include <math.h>

// Problem constants
#define NN 100000
#define DD 128
#define HH 8
#define CC 16
#define EE 800000
#define ETOT (EE + NN)              // 900000
#define OUT_ELEMS (NN * DD)         // 12,800,000
#define EI_ELEMS  (2 * ETOT)        //  1,800,000
#define ALPHA_ELEMS (ETOT * HH)     //  7,200,000
#define NEG_SLOPE 0.2f

// ---------------- device scratch (static: no allocation allowed) -------------
__device__ __align__(16) float    g_h[(size_t)NN * DD];       // 51.2 MB
__device__ __align__(16) float    g_asrc[(size_t)NN * HH];    // 3.2 MB
__device__ __align__(16) float    g_adst[(size_t)NN * HH];    // 3.2 MB
__device__ __align__(16) unsigned g_mx[(size_t)NN * HH];      // 3.2 MB (order-encoded max)
__device__ __align__(16) float    g_denom[(size_t)NN * HH];   // 3.2 MB
__device__ __align__(16) float    g_ex[(size_t)ETOT * HH];    // 28.8 MB
__device__ int g_stride2;   // 1 if edge_index buffer is int64 (read low words, stride 2)

// ---------------- helpers ----------------------------------------------------
__device__ __forceinline__ unsigned fenc(float f) {
    unsigned u = __float_as_uint(f);
    return (u >> 31) ? ~u : (u | 0x80000000u);
}
__device__ __forceinline__ float fdec(unsigned e) {
    return (e >> 31) ? __uint_as_float(e ^ 0x80000000u) : __uint_as_float(~e);
}
__device__ __forceinline__ void ffma2(unsigned long long& acc,
                                      unsigned long long x2,
                                      unsigned long long w2) {
    asm("fma.rn.f32x2 %0, %1, %2, %0;" : "+l"(acc) : "l"(x2), "l"(w2));
}
__device__ __forceinline__ void red_add_v4(float* addr, float a, float b, float c, float d) {
    asm volatile("red.global.add.v4.f32 [%0], {%1,%2,%3,%4};"
                 :: "l"(addr), "f"(a), "f"(b), "f"(c), "f"(d) : "memory");
}
__device__ __forceinline__ float lrelu(float v) {
    return v > 0.f ? v : NEG_SLOPE * v;
}
// Decode edge e -> (src, dst). st2: int64-backed buffer (low words at even idx).
__device__ __forceinline__ void edge_sd(const int* __restrict__ ei, int e, int st2,
                                        int& s, int& d) {
    if (e < EE) {
        if (st2) { s = ei[2 * e]; d = ei[2 * (EE + e)]; }
        else     { s = ei[e];     d = ei[EE + e]; }
    } else {
        s = d = e - EE;
    }
}

// ---------------- K-1: detect int32 vs int64 edge buffer ---------------------
__global__ void detect_kernel(const int* __restrict__ ei) {
    // If buffer holds int64 values < 2^31, every odd 32-bit word is 0.
    int nz = 0;
    #pragma unroll
    for (int i = 0; i < 64; i++) nz |= ei[2 * i + 1];
    g_stride2 = (nz == 0) ? 1 : 0;
}

// ---------------- K0: init scratch + init out to bias + write ei -------------
__global__ void init_kernel(float* __restrict__ out, const float* __restrict__ bias,
                            const int* __restrict__ ei, int writeAll) {
    const int st2 = g_stride2;
    size_t i = (size_t)blockIdx.x * blockDim.x + threadIdx.x;
    size_t stride = (size_t)gridDim.x * blockDim.x;
    for (size_t t = i; t < (size_t)NN * HH; t += stride) {
        g_mx[t] = 0u;
        g_denom[t] = 0.f;
    }
    for (size_t t = i; t < (size_t)OUT_ELEMS; t += stride)
        out[t] = bias[t & 127];
    if (writeAll) {
        for (size_t t = i; t < (size_t)ETOT; t += stride) {
            int s, d;
            edge_sd(ei, (int)t, st2, s, d);
            out[(size_t)OUT_ELEMS + t]        = (float)s;
            out[(size_t)OUT_ELEMS + ETOT + t] = (float)d;
        }
    }
}

// ---------------- K1: h = x @ W  (f32x2 packed FMA, 32-row tiles) ------------
__global__ void __launch_bounds__(128) gemm_kernel(const float* __restrict__ x,
                                                   const float* __restrict__ W) {
    __shared__ __align__(16) float xs[DD * 36];
    const int j = threadIdx.x;
    const int row0 = blockIdx.x * 32;

    #pragma unroll 8
    for (int r = 0; r < 32; r++) {
        int row = row0 + r;
        float v = (row < NN) ? x[(size_t)row * DD + j] : 0.f;
        xs[j * 36 + r] = v;
    }
    __syncthreads();

    unsigned long long acc[16];
    #pragma unroll
    for (int q = 0; q < 16; q++) acc[q] = 0ull;

    #pragma unroll 4
    for (int k = 0; k < DD; k++) {
        float w = W[(size_t)k * DD + j];
        unsigned long long w2;
        asm("mov.b64 %0, {%1,%1};" : "=l"(w2) : "f"(w));
        const ulonglong2* xp = (const ulonglong2*)(&xs[k * 36]);
        #pragma unroll
        for (int q = 0; q < 8; q++) {
            ulonglong2 v = xp[q];
            ffma2(acc[2 * q],     v.x, w2);
            ffma2(acc[2 * q + 1], v.y, w2);
        }
    }

    #pragma unroll
    for (int q = 0; q < 16; q++) {
        float lo, hi;
        asm("mov.b64 {%0,%1}, %2;" : "=f"(lo), "=f"(hi) : "l"(acc[q]));
        int r = 2 * q;
        if (row0 + r     < NN) g_h[(size_t)(row0 + r)     * DD + j] = lo;
        if (row0 + r + 1 < NN) g_h[(size_t)(row0 + r + 1) * DD + j] = hi;
    }
}

// ---------------- K1b: per-(node,head) attention dots ------------------------
__global__ void attn_kernel(const float* __restrict__ att_src,
                            const float* __restrict__ att_dst) {
    int idx = blockIdx.x * blockDim.x + threadIdx.x;
    if (idx >= NN * HH) return;
    int n = idx >> 3, h = idx & 7;
    const float4* hp = (const float4*)(g_h + (size_t)n * DD + h * CC);
    const float4* ap = (const float4*)(att_src + h * CC);
    const float4* bp = (const float4*)(att_dst + h * CC);
    float s = 0.f, d = 0.f;
    #pragma unroll
    for (int q = 0; q < 4; q++) {
        float4 hv = hp[q], av = ap[q], bv = bp[q];
        s += hv.x * av.x + hv.y * av.y + hv.z * av.z + hv.w * av.w;
        d += hv.x * bv.x + hv.y * bv.y + hv.z * bv.z + hv.w * bv.w;
    }
    g_asrc[idx] = s;
    g_adst[idx] = d;
}

// ---------------- K2: segment max over dst (atomicMax, order-encoded) --------
__global__ void max_kernel(const int* __restrict__ ei) {
    int e = blockIdx.x * blockDim.x + threadIdx.x;
    if (e >= ETOT) return;
    int s, d;
    edge_sd(ei, e, g_stride2, s, d);
    const float4* sp = (const float4*)(g_asrc + (size_t)s * 8);
    const float4* dp = (const float4*)(g_adst + (size_t)d * 8);
    unsigned* mp = g_mx + (size_t)d * 8;
    #pragma unroll
    for (int q = 0; q < 2; q++) {
        float4 a = sp[q], b = dp[q];
        atomicMax(mp + 4 * q + 0, fenc(lrelu(a.x + b.x)));
        atomicMax(mp + 4 * q + 1, fenc(lrelu(a.y + b.y)));
        atomicMax(mp + 4 * q + 2, fenc(lrelu(a.z + b.z)));
        atomicMax(mp + 4 * q + 3, fenc(lrelu(a.w + b.w)));
    }
}

// ---------------- K3: ex = exp(logit - mx[dst]); denom += ex (v4 red) --------
__global__ void ex_kernel(const int* __restrict__ ei) {
    int e = blockIdx.x * blockDim.x + threadIdx.x;
    if (e >= ETOT) return;
    int s, d;
    edge_sd(ei, e, g_stride2, s, d);
    const float4* sp = (const float4*)(g_asrc + (size_t)s * 8);
    const float4* dp = (const float4*)(g_adst + (size_t)d * 8);
    const uint4*  mp = (const uint4*)(g_mx + (size_t)d * 8);
    float4* exo = (float4*)(g_ex + (size_t)e * 8);
    float* den = g_denom + (size_t)d * 8;
    #pragma unroll
    for (int q = 0; q < 2; q++) {
        float4 a = sp[q], b = dp[q];
        uint4 m = mp[q];
        float e0 = __expf(lrelu(a.x + b.x) - fdec(m.x));
        float e1 = __expf(lrelu(a.y + b.y) - fdec(m.y));
        float e2 = __expf(lrelu(a.z + b.z) - fdec(m.z));
        float e3 = __expf(lrelu(a.w + b.w) - fdec(m.w));
        exo[q] = make_float4(e0, e1, e2, e3);
        red_add_v4(den + 4 * q, e0, e1, e2, e3);
    }
}

// ---------------- K4: alpha = ex/denom; out[dst] += h[src]*alpha (v4 red) ----
__global__ void scatter_kernel(const int* __restrict__ ei,
                               float* __restrict__ out, int writeAll) {
    int e = blockIdx.x * blockDim.x + threadIdx.x;
    if (e >= ETOT) return;
    int s, d;
    edge_sd(ei, e, g_stride2, s, d);

    const float4* exp_ = (const float4*)(g_ex + (size_t)e * 8);
    const float4* dnp  = (const float4*)(g_denom + (size_t)d * 8);
    float alpha[8];
    #pragma unroll
    for (int q = 0; q < 2; q++) {
        float4 ex = exp_[q], dn = dnp[q];
        alpha[4 * q + 0] = ex.x / (dn.x + 1e-16f);
        alpha[4 * q + 1] = ex.y / (dn.y + 1e-16f);
        alpha[4 * q + 2] = ex.z / (dn.z + 1e-16f);
        alpha[4 * q + 3] = ex.w / (dn.w + 1e-16f);
    }
    if (writeAll) {
        float4* ao = (float4*)(out + (size_t)OUT_ELEMS + EI_ELEMS + (size_t)e * 8);
        ao[0] = make_float4(alpha[0], alpha[1], alpha[2], alpha[3]);
        ao[1] = make_float4(alpha[4], alpha[5], alpha[6], alpha[7]);
    }

    const float4* hp = (const float4*)(g_h + (size_t)s * DD);
    float* ob = out + (size_t)d * DD;
    #pragma unroll
    for (int h = 0; h < HH; h++) {
        float a = alpha[h];
        #pragma unroll
        for (int q = 0; q < 4; q++) {
            float4 hv = hp[h * 4 + q];
            red_add_v4(ob + h * CC + q * 4, hv.x * a, hv.y * a, hv.z * a, hv.w * a);
        }
    }
}

// ---------------- launch ------------------------------------------------------
extern "C" void kernel_launch(void* const* d_in, const int* in_sizes, int n_in,
                              void* d_out, int out_size) {
    const float* x       = (const float*)d_in[0];
    const int*   ei      = (const int*)d_in[1];
    const float* W       = (const float*)d_in[2];
    const float* att_src = (const float*)d_in[3];
    const float* att_dst = (const float*)d_in[4];
    const float* bias    = (const float*)d_in[5];
    float* out = (float*)d_out;

    int writeAll = (out_size >= OUT_ELEMS + EI_ELEMS + ALPHA_ELEMS) ? 1 : 0;

    detect_kernel<<<1, 1>>>(ei);
    init_kernel<<<1024, 256>>>(out, bias, ei, writeAll);
    gemm_kernel<<<(NN + 31) / 32, 128>>>(x, W);
    attn_kernel<<<(NN * HH + 255) / 256, 256>>>(att_src, att_dst);
    max_kernel<<<(ETOT + 255) / 256, 256>>>(ei);
    ex_kernel<<<(ETOT + 255) / 256, 256>>>(ei);
    scatter_kernel<<<(ETOT + 255) / 256, 256>>>(ei, out, writeAll);
}

// round 4
// speedup vs baseline: 2.8056x; 2.8056x over previous
#include <cuda_runtime.h>
#include <math.h>

// Problem constants
#define NN 100000
#define DD 128
#define HH 8
#define CC 16
#define EE 800000
#define ETOT (EE + NN)              // 900000
#define OUT_ELEMS (NN * DD)         // 12,800,000
#define EI_ELEMS  (2 * ETOT)        //  1,800,000
#define ALPHA_ELEMS (ETOT * HH)     //  7,200,000
#define NEG_SLOPE 0.2f

#define SB 512
#define NB1 ((NN + SB - 1) / SB)    // 196 scan blocks

// ---------------- device scratch (static; 16B-aligned for vector ops) --------
__device__ __align__(16) float g_h[(size_t)NN * DD];      // 51.2 MB
__device__ __align__(16) float g_asrc[(size_t)NN * HH];   // 3.2 MB
__device__ __align__(16) float g_adst[(size_t)NN * HH];   // 3.2 MB
__device__ __align__(16) float g_wa[DD * 16];             // fused W@att (src|dst)
__device__ int g_cnt[NN];
__device__ int g_rowptr[NN + 1];
__device__ int g_fillpos[NN];
__device__ int g_bsum[256];
__device__ int g_boff[256];
__device__ int g_esrc[ETOT];
__device__ int g_eid[ETOT];
__device__ int g_stride2;   // 1 if edge buffer is int64-backed (low words, stride 2)

// ---------------- helpers ----------------------------------------------------
__device__ __forceinline__ void ffma2(unsigned long long& acc,
                                      unsigned long long x2,
                                      unsigned long long w2) {
    asm("fma.rn.f32x2 %0, %1, %2, %0;" : "+l"(acc) : "l"(x2), "l"(w2));
}
__device__ __forceinline__ float lrelu(float v) {
    return v > 0.f ? v : NEG_SLOPE * v;
}
__device__ __forceinline__ void edge_sd(const int* __restrict__ ei, int e, int st2,
                                        int& s, int& d) {
    if (e < EE) {
        if (st2) { s = ei[2 * e]; d = ei[2 * (EE + e)]; }
        else     { s = ei[e];     d = ei[EE + e]; }
    } else {
        s = d = e - EE;
    }
}

// ---------------- detect int32 vs int64 edge buffer --------------------------
__global__ void detect_kernel(const int* __restrict__ ei) {
    int nz = 0;
    #pragma unroll
    for (int i = 0; i < 64; i++) nz |= ei[2 * i + 1];
    g_stride2 = (nz == 0) ? 1 : 0;
}

// ---------------- init: zero histogram + (optional) ei copy ------------------
__global__ void init_kernel(float* __restrict__ out, const int* __restrict__ ei,
                            int writeAll) {
    const int st2 = g_stride2;
    int i = blockIdx.x * blockDim.x + threadIdx.x;
    int stride = gridDim.x * blockDim.x;
    for (int t = i; t < NN; t += stride) g_cnt[t] = 0;
    if (writeAll) {
        for (int t = i; t < ETOT; t += stride) {
            int s, d;
            edge_sd(ei, t, st2, s, d);
            out[(size_t)OUT_ELEMS + t]        = (float)s;
            out[(size_t)OUT_ELEMS + ETOT + t] = (float)d;
        }
    }
}

// ---------------- prep: Wa[k][c] = sum_c' W[k][h*16+c'] * att[h][c'] ---------
// cols 0..7 = per-head att_src dot, cols 8..15 = att_dst.
__global__ void prep_wa_kernel(const float* __restrict__ W,
                               const float* __restrict__ as,
                               const float* __restrict__ ad) {
    int k = threadIdx.x;   // 0..127
    #pragma unroll
    for (int h = 0; h < HH; h++) {
        float s1 = 0.f, s2 = 0.f;
        #pragma unroll
        for (int c = 0; c < CC; c++) {
            float w = W[(size_t)k * DD + h * CC + c];
            s1 += w * as[h * CC + c];
            s2 += w * ad[h * CC + c];
        }
        g_wa[k * 16 + h]     = s1;
        g_wa[k * 16 + 8 + h] = s2;
    }
}

// ---------------- GEMM: h = x @ W (f32x2 packed FMA, 32-row tiles) -----------
__global__ void __launch_bounds__(128) gemm_kernel(const float* __restrict__ x,
                                                   const float* __restrict__ W) {
    __shared__ __align__(16) float xs[DD * 36];
    const int j = threadIdx.x;
    const int row0 = blockIdx.x * 32;

    #pragma unroll 8
    for (int r = 0; r < 32; r++) {
        int row = row0 + r;
        float v = (row < NN) ? x[(size_t)row * DD + j] : 0.f;
        xs[j * 36 + r] = v;
    }
    __syncthreads();

    unsigned long long acc[16];
    #pragma unroll
    for (int q = 0; q < 16; q++) acc[q] = 0ull;

    #pragma unroll 4
    for (int k = 0; k < DD; k++) {
        float w = W[(size_t)k * DD + j];
        unsigned long long w2;
        asm("mov.b64 %0, {%1,%1};" : "=l"(w2) : "f"(w));
        const ulonglong2* xp = (const ulonglong2*)(&xs[k * 36]);
        #pragma unroll
        for (int q = 0; q < 8; q++) {
            ulonglong2 v = xp[q];
            ffma2(acc[2 * q],     v.x, w2);
            ffma2(acc[2 * q + 1], v.y, w2);
        }
    }

    #pragma unroll
    for (int q = 0; q < 16; q++) {
        float lo, hi;
        asm("mov.b64 {%0,%1}, %2;" : "=f"(lo), "=f"(hi) : "l"(acc[q]));
        int r = 2 * q;
        if (row0 + r     < NN) g_h[(size_t)(row0 + r)     * DD + j] = lo;
        if (row0 + r + 1 < NN) g_h[(size_t)(row0 + r + 1) * DD + j] = hi;
    }
}

// ---------------- attention dots: a = x @ Wa (skinny GEMM) -------------------
// Block: 128 threads, 32 rows. Warp w handles k-range [w*32, w*32+32).
__global__ void __launch_bounds__(128) attn2_kernel(const float* __restrict__ x) {
    __shared__ __align__(16) float xs[DD * 36];
    __shared__ __align__(16) float wa_s[DD * 16];
    __shared__ float ps[4 * 32 * 17];          // [warp][row][col] padded
    const int j = threadIdx.x;
    const int row0 = blockIdx.x * 32;

    #pragma unroll 8
    for (int r = 0; r < 32; r++) {
        int row = row0 + r;
        float v = (row < NN) ? x[(size_t)row * DD + j] : 0.f;
        xs[j * 36 + r] = v;
    }
    #pragma unroll
    for (int q = 0; q < 16; q++) wa_s[q * 128 + j] = g_wa[q * 128 + j];
    __syncthreads();

    const int lane = j & 31;     // row
    const int w    = j >> 5;     // k-chunk
    float s[16];
    #pragma unroll
    for (int c = 0; c < 16; c++) s[c] = 0.f;
    #pragma unroll 4
    for (int kk = 0; kk < 32; kk++) {
        int k = w * 32 + kk;
        float xv = xs[k * 36 + lane];
        const float4* wp = (const float4*)(&wa_s[k * 16]);
        #pragma unroll
        for (int q = 0; q < 4; q++) {
            float4 wv = wp[q];
            s[4 * q + 0] += xv * wv.x;
            s[4 * q + 1] += xv * wv.y;
            s[4 * q + 2] += xv * wv.z;
            s[4 * q + 3] += xv * wv.w;
        }
    }
    #pragma unroll
    for (int c = 0; c < 16; c++) ps[w * 544 + lane * 17 + c] = s[c];
    __syncthreads();

    // reduce 4 partials; thread j handles outputs j*4 .. j*4+3
    #pragma unroll
    for (int q = 0; q < 4; q++) {
        int o = j * 4 + q;
        int r = o >> 4, c = o & 15;
        float v = ps[0 * 544 + r * 17 + c] + ps[1 * 544 + r * 17 + c]
                + ps[2 * 544 + r * 17 + c] + ps[3 * 544 + r * 17 + c];
        int row = row0 + r;
        if (row < NN) {
            if (c < 8) g_asrc[(size_t)row * 8 + c] = v;
            else       g_adst[(size_t)row * 8 + (c - 8)] = v;
        }
    }
}

// ---------------- CSR build --------------------------------------------------
__global__ void hist_kernel(const int* __restrict__ ei) {
    int e = blockIdx.x * blockDim.x + threadIdx.x;
    if (e >= ETOT) return;
    int s, d;
    edge_sd(ei, e, g_stride2, s, d);
    atomicAdd(&g_cnt[d], 1);
}

__global__ void scan1_kernel() {
    __shared__ int sm[SB];
    int tid = threadIdx.x;
    int gid = blockIdx.x * SB + tid;
    int v = (gid < NN) ? g_cnt[gid] : 0;
    sm[tid] = v;
    __syncthreads();
    for (int off = 1; off < SB; off <<= 1) {
        int t = (tid >= off) ? sm[tid - off] : 0;
        __syncthreads();
        sm[tid] += t;
        __syncthreads();
    }
    if (gid < NN) g_rowptr[gid] = sm[tid] - v;
    if (tid == SB - 1) g_bsum[blockIdx.x] = sm[tid];
}

__global__ void scan2_kernel() {
    __shared__ int sm[256];
    int tid = threadIdx.x;
    int v = (tid < NB1) ? g_bsum[tid] : 0;
    sm[tid] = v;
    __syncthreads();
    for (int off = 1; off < 256; off <<= 1) {
        int t = (tid >= off) ? sm[tid - off] : 0;
        __syncthreads();
        sm[tid] += t;
        __syncthreads();
    }
    g_boff[tid] = sm[tid] - v;
}

__global__ void scan3_kernel() {
    int tid = threadIdx.x;
    int gid = blockIdx.x * SB + tid;
    if (gid < NN) {
        int r = g_rowptr[gid] + g_boff[blockIdx.x];
        g_rowptr[gid] = r;
        g_fillpos[gid] = r;
    }
    if (blockIdx.x == 0 && tid == 0) g_rowptr[NN] = ETOT;
}

__global__ void fill_kernel(const int* __restrict__ ei) {
    int e = blockIdx.x * blockDim.x + threadIdx.x;
    if (e >= ETOT) return;
    int s, d;
    edge_sd(ei, e, g_stride2, s, d);
    int pos = atomicAdd(&g_fillpos[d], 1);
    g_esrc[pos] = s;
    g_eid[pos] = e;
}

// ---------------- fused softmax + gather: one warp per dst node --------------
__global__ void __launch_bounds__(256) gather_kernel(float* __restrict__ out,
                                                     const float* __restrict__ bias,
                                                     int writeAll) {
    int gw = (blockIdx.x * blockDim.x + threadIdx.x) >> 5;
    int lane = threadIdx.x & 31;
    if (gw >= NN) return;
    const int d = gw;
    const int start = g_rowptr[d];
    const int end   = g_rowptr[d + 1];
    const int h = lane >> 2;                        // head for my 4 channels

    float adh = g_adst[(size_t)d * 8 + h];

    // pass 1: online (max, sum) per head
    float m = -3.402823466e38f, ssum = 0.f;
    for (int i = start; i < end; i++) {
        int s = g_esrc[i];
        float lg = lrelu(g_asrc[(size_t)s * 8 + h] + adh);
        float nm = fmaxf(m, lg);
        ssum = ssum * __expf(m - nm) + __expf(lg - nm);
        m = nm;
    }
    float inv = 1.f / (ssum + 1e-16f);

    // pass 2: alpha-weighted accumulation of h[src]
    float4 acc = make_float4(0.f, 0.f, 0.f, 0.f);
    for (int i = start; i < end; i++) {
        int s = g_esrc[i];
        float lg = lrelu(g_asrc[(size_t)s * 8 + h] + adh);
        float al = __expf(lg - m) * inv;
        if (writeAll && (lane & 3) == 0) {
            int eid = g_eid[i];
            out[(size_t)OUT_ELEMS + EI_ELEMS + (size_t)eid * 8 + h] = al;
        }
        float4 hv = *(const float4*)(g_h + (size_t)s * DD + lane * 4);
        acc.x += al * hv.x;
        acc.y += al * hv.y;
        acc.z += al * hv.z;
        acc.w += al * hv.w;
    }

    float4 bv = *(const float4*)(bias + lane * 4);
    acc.x += bv.x; acc.y += bv.y; acc.z += bv.z; acc.w += bv.w;
    *(float4*)(out + (size_t)d * DD + lane * 4) = acc;
}

// ---------------- launch ------------------------------------------------------
extern "C" void kernel_launch(void* const* d_in, const int* in_sizes, int n_in,
                              void* d_out, int out_size) {
    const float* x       = (const float*)d_in[0];
    const int*   ei      = (const int*)d_in[1];
    const float* W       = (const float*)d_in[2];
    const float* att_src = (const float*)d_in[3];
    const float* att_dst = (const float*)d_in[4];
    const float* bias    = (const float*)d_in[5];
    float* out = (float*)d_out;

    int writeAll = (out_size >= OUT_ELEMS + EI_ELEMS + ALPHA_ELEMS) ? 1 : 0;

    detect_kernel<<<1, 1>>>(ei);
    init_kernel<<<512, 256>>>(out, ei, writeAll);
    prep_wa_kernel<<<1, 128>>>(W, att_src, att_dst);
    gemm_kernel<<<(NN + 31) / 32, 128>>>(x, W);
    attn2_kernel<<<(NN + 31) / 32, 128>>>(x);
    hist_kernel<<<(ETOT + 255) / 256, 256>>>(ei);
    scan1_kernel<<<NB1, SB>>>();
    scan2_kernel<<<1, 256>>>();
    scan3_kernel<<<NB1, SB>>>();
    fill_kernel<<<(ETOT + 255) / 256, 256>>>(ei);
    gather_kernel<<<(NN * 32 + 255) / 256, 256>>>(out, bias, writeAll);
}